// round 1
// baseline (speedup 1.0000x reference)
#include <cuda_runtime.h>
#include <cstdint>
#include <math.h>

// Problem constants
#define B_   2
#define HQ_  16
#define S_   2048
#define D_   64
#define DV_  128
// derived
#define GROUPS 32          // B * HQ groups for group norm (each = contiguous 131072 elems)
#define GROUP_ELEMS 131072 // 1024 * 128
#define PPG 8              // partial blocks per group

// Scratch (no allocations allowed -> device globals)
static __device__ float  g_o[(size_t)B_ * HQ_ * S_ * DV_];   // per-head attention output, 33.5MB
static __device__ double g_psum[GROUPS * PPG];
static __device__ double g_psq [GROUPS * PPG];
static __device__ float  g_mean[GROUPS];
static __device__ float  g_istd[GROUPS];
static __device__ float  g_lam;

// ---------------------------------------------------------------------------
// helpers
// ---------------------------------------------------------------------------
__device__ __forceinline__ uint32_t f2tf(float x) {
    uint32_t r;
    asm("cvt.rna.tf32.f32 %0, %1;" : "=r"(r) : "f"(x));
    return r;
}

__device__ __forceinline__ void mma8(float& c0, float& c1, float& c2, float& c3,
                                     uint32_t a0, uint32_t a1, uint32_t a2, uint32_t a3,
                                     uint32_t b0, uint32_t b1) {
    asm volatile(
        "mma.sync.aligned.m16n8k8.row.col.f32.tf32.tf32.f32 "
        "{%0,%1,%2,%3},{%4,%5,%6,%7},{%8,%9},{%0,%1,%2,%3};"
        : "+f"(c0), "+f"(c1), "+f"(c2), "+f"(c3)
        : "r"(a0), "r"(a1), "r"(a2), "r"(a3), "r"(b0), "r"(b1));
}

// ---------------------------------------------------------------------------
// Flash attention per head (ghostmax). grid (32 qtiles, 16 heads, 2 batch),
// 128 threads (4 warps x m16 rows). BM = BN = 64.
// ---------------------------------------------------------------------------
__global__ __launch_bounds__(128)
void attn_kernel(const float* __restrict__ q,
                 const float* __restrict__ k,
                 const float* __restrict__ v) {
    __shared__ float Ksh[64 * 64];    // 16KB, XOR-swizzled: col' = d ^ ((row&7)<<2)
    __shared__ float Vsh[64 * 128];   // 32KB, XOR-swizzled: col' = dv ^ ((row&3)<<3)

    const int tid  = threadIdx.x;
    const int lane = tid & 31;
    const int wm   = tid >> 5;        // warp id: rows [wm*16, wm*16+16)
    const int r    = lane >> 2;       // 0..7
    const int qd   = lane & 3;        // 0..3
    const unsigned F = 0xffffffffu;

    const int qt = blockIdx.x;
    const int h  = blockIdx.y;
    const int b  = blockIdx.z;
    const int hp = h >> 1;
    const float scale = 0.125f;       // 1/sqrt(64)

    // ---- stage Q tile into Ksh (scaled, tf32-rounded, swizzled) ----
    {
        const float4* qp = reinterpret_cast<const float4*>(
            q + (((size_t)b * HQ_ + h) * S_ + (size_t)qt * 64) * D_);
        float4* Ks4 = reinterpret_cast<float4*>(Ksh);
#pragma unroll
        for (int i0 = 0; i0 < 8; i0++) {
            int i = i0 * 128 + tid;
            int row = i >> 4, c4 = i & 15;
            float4 val = qp[i];
            val.x = __uint_as_float(f2tf(val.x * scale));
            val.y = __uint_as_float(f2tf(val.y * scale));
            val.z = __uint_as_float(f2tf(val.z * scale));
            val.w = __uint_as_float(f2tf(val.w * scale));
            Ks4[(row << 4) + (c4 ^ (row & 7))] = val;
        }
    }
    __syncthreads();

    // ---- extract Q A-fragments (m16n8k8: a0=(r,c), a1=(r+8,c), a2=(r,c+4), a3=(r+8,c+4)) ----
    uint32_t qa[8][4];
    {
        int row0 = wm * 16 + r;
        int row1 = row0 + 8;
        int swz = r << 2; // (row&7)<<2 == r<<2 for both rows
#pragma unroll
        for (int kk = 0; kk < 8; kk++) {
            int d0 = kk * 8 + qd, d1 = d0 + 4;
            qa[kk][0] = __float_as_uint(Ksh[(row0 << 6) + (d0 ^ swz)]);
            qa[kk][1] = __float_as_uint(Ksh[(row1 << 6) + (d0 ^ swz)]);
            qa[kk][2] = __float_as_uint(Ksh[(row0 << 6) + (d1 ^ swz)]);
            qa[kk][3] = __float_as_uint(Ksh[(row1 << 6) + (d1 ^ swz)]);
        }
    }

    float oc[16][4];
#pragma unroll
    for (int j = 0; j < 16; j++) { oc[j][0] = 0.f; oc[j][1] = 0.f; oc[j][2] = 0.f; oc[j][3] = 0.f; }

    // ghostmax online state: implicit zero logit -> m = 0, l = 1
    float m0 = 0.f, m1 = 0.f, l0 = 1.f, l1 = 1.f;

    const float4* kbase = reinterpret_cast<const float4*>(k + (((size_t)b * HQ_ + h) * S_) * D_);
    const float4* vbase = reinterpret_cast<const float4*>(v + (((size_t)b * (HQ_ / 2) + hp) * S_) * DV_);

    for (int kt = 0; kt <= qt; kt++) {
        __syncthreads();
        // ---- stage K tile (tf32-round during staging) ----
        {
            const float4* kp = kbase + (size_t)kt * 64 * 16;
            float4* Ks4 = reinterpret_cast<float4*>(Ksh);
#pragma unroll
            for (int i0 = 0; i0 < 8; i0++) {
                int i = i0 * 128 + tid;
                int row = i >> 4, c4 = i & 15;
                float4 val = kp[i];
                val.x = __uint_as_float(f2tf(val.x));
                val.y = __uint_as_float(f2tf(val.y));
                val.z = __uint_as_float(f2tf(val.z));
                val.w = __uint_as_float(f2tf(val.w));
                Ks4[(row << 4) + (c4 ^ (row & 7))] = val;
            }
            const float4* vp = vbase + (size_t)kt * 64 * 32;
            float4* Vs4 = reinterpret_cast<float4*>(Vsh);
#pragma unroll
            for (int i0 = 0; i0 < 16; i0++) {
                int i = i0 * 128 + tid;
                int row = i >> 5, c4 = i & 31;
                float4 val = vp[i];
                val.x = __uint_as_float(f2tf(val.x));
                val.y = __uint_as_float(f2tf(val.y));
                val.z = __uint_as_float(f2tf(val.z));
                val.w = __uint_as_float(f2tf(val.w));
                Vs4[(row << 5) + (c4 ^ ((row & 3) << 1))] = val;
            }
        }
        __syncthreads();

        // ---- S = Q @ K^T (8 n-tiles of m16n8, 8 k-steps) ----
        float sc[8][4];
#pragma unroll
        for (int jn = 0; jn < 8; jn++) {
            float c0 = 0.f, c1 = 0.f, c2 = 0.f, c3 = 0.f;
            int keyr = jn * 8 + r;       // B frag n index = lane/4
            int swz = r << 2;            // (keyr&7)<<2 == r<<2
#pragma unroll
            for (int kk = 0; kk < 8; kk++) {
                uint32_t b0 = __float_as_uint(Ksh[(keyr << 6) + ((kk * 8 + qd) ^ swz)]);
                uint32_t b1 = __float_as_uint(Ksh[(keyr << 6) + ((kk * 8 + qd + 4) ^ swz)]);
                mma8(c0, c1, c2, c3, qa[kk][0], qa[kk][1], qa[kk][2], qa[kk][3], b0, b1);
            }
            sc[jn][0] = c0; sc[jn][1] = c1; sc[jn][2] = c2; sc[jn][3] = c3;
        }

        // ---- causal mask on the diagonal tile ----
        if (kt == qt) {
            int row0 = wm * 16 + r;
#pragma unroll
            for (int jn = 0; jn < 8; jn++) {
                int c = jn * 8 + 2 * qd;
                if (c     > row0)     sc[jn][0] = -1e30f;
                if (c + 1 > row0)     sc[jn][1] = -1e30f;
                if (c     > row0 + 8) sc[jn][2] = -1e30f;
                if (c + 1 > row0 + 8) sc[jn][3] = -1e30f;
            }
        }

        // ---- online ghost-softmax update ----
        float rm0 = -1e30f, rm1 = -1e30f;
#pragma unroll
        for (int jn = 0; jn < 8; jn++) {
            rm0 = fmaxf(rm0, fmaxf(sc[jn][0], sc[jn][1]));
            rm1 = fmaxf(rm1, fmaxf(sc[jn][2], sc[jn][3]));
        }
        rm0 = fmaxf(rm0, __shfl_xor_sync(F, rm0, 1));
        rm0 = fmaxf(rm0, __shfl_xor_sync(F, rm0, 2));
        rm1 = fmaxf(rm1, __shfl_xor_sync(F, rm1, 1));
        rm1 = fmaxf(rm1, __shfl_xor_sync(F, rm1, 2));
        float mn0 = fmaxf(m0, rm0), mn1 = fmaxf(m1, rm1);
        float al0 = __expf(m0 - mn0), al1 = __expf(m1 - mn1);
        m0 = mn0; m1 = mn1;

        float rs0 = 0.f, rs1 = 0.f;
#pragma unroll
        for (int jn = 0; jn < 8; jn++) {
            sc[jn][0] = __expf(sc[jn][0] - mn0); rs0 += sc[jn][0];
            sc[jn][1] = __expf(sc[jn][1] - mn0); rs0 += sc[jn][1];
            sc[jn][2] = __expf(sc[jn][2] - mn1); rs1 += sc[jn][2];
            sc[jn][3] = __expf(sc[jn][3] - mn1); rs1 += sc[jn][3];
        }
        rs0 += __shfl_xor_sync(F, rs0, 1);
        rs0 += __shfl_xor_sync(F, rs0, 2);
        rs1 += __shfl_xor_sync(F, rs1, 1);
        rs1 += __shfl_xor_sync(F, rs1, 2);
        l0 = l0 * al0 + rs0;
        l1 = l1 * al1 + rs1;

#pragma unroll
        for (int jo = 0; jo < 16; jo++) {
            oc[jo][0] *= al0; oc[jo][1] *= al0;
            oc[jo][2] *= al1; oc[jo][3] *= al1;
        }

        // ---- O += P @ V (P A-frags built via intra-quad shuffles from sc) ----
        const int srcA = (lane & ~3) | (qd >> 1);
        const int srcB = srcA + 2;
        const bool odd = qd & 1;
#pragma unroll
        for (int kk2 = 0; kk2 < 8; kk2++) {
            float x00 = __shfl_sync(F, sc[kk2][0], srcA);
            float x01 = __shfl_sync(F, sc[kk2][1], srcA);
            float x20 = __shfl_sync(F, sc[kk2][2], srcA);
            float x21 = __shfl_sync(F, sc[kk2][3], srcA);
            float y00 = __shfl_sync(F, sc[kk2][0], srcB);
            float y01 = __shfl_sync(F, sc[kk2][1], srcB);
            float y20 = __shfl_sync(F, sc[kk2][2], srcB);
            float y21 = __shfl_sync(F, sc[kk2][3], srcB);
            uint32_t pa0 = f2tf(odd ? x01 : x00); // P[r   ][kk2*8+qd  ]
            uint32_t pa1 = f2tf(odd ? x21 : x20); // P[r+8 ][kk2*8+qd  ]
            uint32_t pa2 = f2tf(odd ? y01 : y00); // P[r   ][kk2*8+qd+4]
            uint32_t pa3 = f2tf(odd ? y21 : y20); // P[r+8 ][kk2*8+qd+4]
            int vr0 = kk2 * 8 + qd;
            int swzv = qd << 3; // (vrow&3)<<3, same for vr0 and vr0+4
#pragma unroll
            for (int jo = 0; jo < 16; jo++) {
                uint32_t b0 = __float_as_uint(Vsh[(vr0 << 7)       + ((jo * 8 + r) ^ swzv)]);
                uint32_t b1 = __float_as_uint(Vsh[((vr0 + 4) << 7) + ((jo * 8 + r) ^ swzv)]);
                mma8(oc[jo][0], oc[jo][1], oc[jo][2], oc[jo][3], pa0, pa1, pa2, pa3, b0, b1);
            }
        }
    }

    // ---- epilogue: divide by l, stage via smem, coalesced store ----
    __syncthreads(); // Vsh reads done
    {
        float inv0 = 1.f / l0, inv1 = 1.f / l1;
        int row0 = wm * 16 + r, row1 = row0 + 8;
        int s0 = (r & 3) << 3;
#pragma unroll
        for (int jo = 0; jo < 16; jo++) {
            int c = jo * 8 + 2 * qd;
            int cs = c ^ s0; // even; (c+1)^s0 == cs+1
            *reinterpret_cast<float2*>(&Vsh[(row0 << 7) + cs]) =
                make_float2(oc[jo][0] * inv0, oc[jo][1] * inv0);
            *reinterpret_cast<float2*>(&Vsh[(row1 << 7) + cs]) =
                make_float2(oc[jo][2] * inv1, oc[jo][3] * inv1);
        }
    }
    __syncthreads();
    {
        float4* op = reinterpret_cast<float4*>(
            g_o + (((size_t)b * HQ_ + h) * S_ + (size_t)qt * 64) * DV_);
        const float4* Vs4 = reinterpret_cast<const float4*>(Vsh);
#pragma unroll
        for (int i0 = 0; i0 < 16; i0++) {
            int i = i0 * 128 + tid;
            int row = i >> 5, c4 = i & 31;
            op[i] = Vs4[(row << 5) + (c4 ^ ((row & 3) << 1))];
        }
    }
}

// ---------------------------------------------------------------------------
// lambda = exp(dot(lq1,lk1)) - exp(dot(lq2,lk2)) + 0.8
// ---------------------------------------------------------------------------
__global__ void lam_kernel(const float* __restrict__ lq1, const float* __restrict__ lk1,
                           const float* __restrict__ lq2, const float* __restrict__ lk2) {
    __shared__ float a[64], c[64];
    int t = threadIdx.x;
    a[t] = lq1[t] * lk1[t];
    c[t] = lq2[t] * lk2[t];
    __syncthreads();
    if (t == 0) {
        float s1 = 0.f, s2 = 0.f;
        for (int j = 0; j < 64; j++) { s1 += a[j]; s2 += c[j]; }
        g_lam = expf(s1) - expf(s2) + 0.8f;
    }
}

// ---------------------------------------------------------------------------
// Group-norm stats. Group g = b*16 + hp*2 + (s>=1024) is a CONTIGUOUS
// 131072-element chunk of diff = o[2hp] - lam*o[2hp+1]. Deterministic
// two-stage reduction (fixed slots, no atomics).
// ---------------------------------------------------------------------------
__global__ void stats_partial_kernel() {
    int g = blockIdx.x >> 3, p = blockIdx.x & 7;
    int b = g >> 4, gg = g & 15, hp = gg >> 1, half = gg & 1;
    const float* o0 = g_o + (((size_t)(b * 16 + 2 * hp)) * S_ + (size_t)half * 1024) * DV_;
    const float* o1 = o0 + (size_t)S_ * DV_;
    float lam = g_lam;
    double sum = 0.0, sq = 0.0;
    int base = p * (GROUP_ELEMS / PPG);
    for (int j = threadIdx.x; j < GROUP_ELEMS / PPG; j += 256) {
        float d = o0[base + j] - lam * o1[base + j];
        sum += (double)d;
        sq  += (double)d * (double)d;
    }
    __shared__ double ssum[256], ssq[256];
    ssum[threadIdx.x] = sum; ssq[threadIdx.x] = sq;
    __syncthreads();
    for (int st = 128; st > 0; st >>= 1) {
        if (threadIdx.x < st) {
            ssum[threadIdx.x] += ssum[threadIdx.x + st];
            ssq[threadIdx.x]  += ssq[threadIdx.x + st];
        }
        __syncthreads();
    }
    if (threadIdx.x == 0) {
        g_psum[blockIdx.x] = ssum[0];
        g_psq[blockIdx.x]  = ssq[0];
    }
}

__global__ void stats_final_kernel() {
    int g = threadIdx.x; // 32 groups
    double s = 0.0, sq = 0.0;
    for (int p = 0; p < PPG; p++) { s += g_psum[g * PPG + p]; sq += g_psq[g * PPG + p]; }
    double mean = s / (double)GROUP_ELEMS;
    double var  = sq / (double)GROUP_ELEMS - mean * mean;
    g_mean[g] = (float)mean;
    g_istd[g] = (float)(1.0 / sqrt(var + 1e-5));
}

// ---------------------------------------------------------------------------
// diff + normalize + affine + *(1-0.8). Output flat layout == (b,hp,s,dv),
// gn channel c = hp*128 + s/16, group g = b*16 + hp*2 + (s>=1024).
// ---------------------------------------------------------------------------
__global__ void normalize_kernel(const float* __restrict__ gw, const float* __restrict__ gb,
                                 float* __restrict__ out) {
    int i = blockIdx.x * 256 + threadIdx.x;
    int dv = i & 127;
    int s  = (i >> 7) & 2047;
    int hp = (i >> 18) & 7;
    int b  = i >> 21;
    int g  = b * 16 + hp * 2 + (s >> 10);
    int c  = hp * 128 + (s >> 4);
    size_t i0 = (((size_t)(b * 16 + 2 * hp)) * S_ + s) * DV_ + dv;
    float lam = g_lam;
    float d = g_o[i0] - lam * g_o[i0 + (size_t)S_ * DV_];
    out[i] = ((d - g_mean[g]) * g_istd[g] * gw[c] + gb[c]) * 0.2f;
}

// ---------------------------------------------------------------------------
extern "C" void kernel_launch(void* const* d_in, const int* in_sizes, int n_in,
                              void* d_out, int out_size) {
    const float* q   = (const float*)d_in[0];
    const float* k   = (const float*)d_in[1];
    const float* v   = (const float*)d_in[2];
    const float* lq1 = (const float*)d_in[3];
    const float* lk1 = (const float*)d_in[4];
    const float* lq2 = (const float*)d_in[5];
    const float* lk2 = (const float*)d_in[6];
    const float* gw  = (const float*)d_in[7];
    const float* gb  = (const float*)d_in[8];
    float* out = (float*)d_out;

    attn_kernel<<<dim3(S_ / 64, HQ_, B_), 128>>>(q, k, v);
    lam_kernel<<<1, 64>>>(lq1, lk1, lq2, lk2);
    stats_partial_kernel<<<GROUPS * PPG, 256>>>();
    stats_final_kernel<<<1, 32>>>();
    normalize_kernel<<<(B_ * (HQ_ / 2) * S_ * DV_) / 256, 256>>>(gw, gb, out);
}

// round 2
// speedup vs baseline: 1.0034x; 1.0034x over previous
#include <cuda_runtime.h>
#include <cstdint>
#include <math.h>

// Problem constants
#define B_   2
#define HQ_  16
#define S_   2048
#define D_   64
#define DV_  128
#define GROUPS 32
#define GROUP_ELEMS 131072
#define PPG 8

// Scratch (no allocations allowed -> device globals)
static __device__ float  g_o[(size_t)B_ * HQ_ * S_ * DV_];   // 33.5MB
static __device__ double g_psum[GROUPS * PPG];
static __device__ double g_psq [GROUPS * PPG];
static __device__ float  g_mean[GROUPS];
static __device__ float  g_istd[GROUPS];
static __device__ float  g_lam;

// ---------------------------------------------------------------------------
__device__ __forceinline__ uint32_t f2tf(float x) {
    uint32_t r;
    asm("cvt.rna.tf32.f32 %0, %1;" : "=r"(r) : "f"(x));
    return r;
}

__device__ __forceinline__ void mma8(float& c0, float& c1, float& c2, float& c3,
                                     uint32_t a0, uint32_t a1, uint32_t a2, uint32_t a3,
                                     uint32_t b0, uint32_t b1) {
    asm volatile(
        "mma.sync.aligned.m16n8k8.row.col.f32.tf32.tf32.f32 "
        "{%0,%1,%2,%3},{%4,%5,%6,%7},{%8,%9},{%0,%1,%2,%3};"
        : "+f"(c0), "+f"(c1), "+f"(c2), "+f"(c3)
        : "r"(a0), "r"(a1), "r"(a2), "r"(a3), "r"(b0), "r"(b1));
}

#define CP16(dst, src) asm volatile("cp.async.cg.shared.global [%0], [%1], 16;" :: "r"(dst), "l"(src))
#define CP_COMMIT()    asm volatile("cp.async.commit_group;")
#define CP_WAIT1()     asm volatile("cp.async.wait_group 1;")
#define CP_WAIT0()     asm volatile("cp.async.wait_group 0;")

// ---------------------------------------------------------------------------
// Flash attention, BM=128, BN=64, 256 threads (8 warps x 16 rows),
// cp.async double-buffered K/V tiles. grid (16 qtiles desc, 16 heads, 2 batch).
// Dynamic smem 128KB: Qs[128x64] | Ks[2][64x64] | Vs[2][64x128]
// ---------------------------------------------------------------------------
__global__ __launch_bounds__(256, 1)
void attn_kernel(const float* __restrict__ q,
                 const float* __restrict__ k,
                 const float* __restrict__ v) {
    extern __shared__ float sm[];
    float* Qs = sm;            // 8192 floats
    float* Ks = sm + 8192;     // 2 * 4096
    float* Vs = sm + 16384;    // 2 * 8192
    float* Ost = sm + 16384;   // epilogue alias (16384 floats = 128x128)

    const int tid  = threadIdx.x;
    const int lane = tid & 31;
    const int wm   = tid >> 5;        // 0..7, rows [wm*16, wm*16+16)
    const int r    = lane >> 2;
    const int qd   = lane & 3;
    const unsigned F = 0xffffffffu;

    const int qt = 15 - blockIdx.x;   // heavy tiles first
    const int h  = blockIdx.y;
    const int b  = blockIdx.z;
    const int hp = h >> 1;
    const float scale = 0.125f;

    uint32_t smb;
    asm("{ .reg .u64 t; cvta.to.shared.u64 t, %1; cvt.u32.u64 %0, t; }" : "=r"(smb) : "l"(sm));
    const uint32_t ksb = smb + 32768u;   // Ks bytes
    const uint32_t vsb = smb + 65536u;   // Vs bytes

    const float4* qg = reinterpret_cast<const float4*>(
        q + (((size_t)b * HQ_ + h) * S_ + (size_t)qt * 128) * D_);
    const float4* kg = reinterpret_cast<const float4*>(k + (((size_t)b * HQ_ + h) * S_) * D_);
    const float4* vg = reinterpret_cast<const float4*>(v + (((size_t)b * (HQ_ / 2) + hp) * S_) * DV_);

    // ---- prologue: group 1 = Q (2048 f4) + K0 (1024 f4) + V0 (2048 f4) ----
#pragma unroll
    for (int i0 = 0; i0 < 8; i0++) {
        int i = i0 * 256 + tid;
        int row = i >> 4, c4 = i & 15;
        CP16(smb + (((row << 4) + (c4 ^ (row & 7))) << 4), qg + i);
    }
#pragma unroll
    for (int i0 = 0; i0 < 4; i0++) {
        int i = i0 * 256 + tid;
        int row = i >> 4, c4 = i & 15;
        CP16(ksb + (((row << 4) + (c4 ^ (row & 7))) << 4), kg + i);
    }
#pragma unroll
    for (int i0 = 0; i0 < 8; i0++) {
        int i = i0 * 256 + tid;
        int row = i >> 5, c4 = i & 31;
        CP16(vsb + (((row << 5) + (c4 ^ ((row & 3) << 1))) << 4), vg + i);
    }
    CP_COMMIT();

    const int ktmax = 2 * qt + 1;
    const int W0 = qt * 128 + wm * 16;   // warp's first global row

    uint32_t qa[8][4];
    float oc[16][4];
#pragma unroll
    for (int j = 0; j < 16; j++) { oc[j][0] = 0.f; oc[j][1] = 0.f; oc[j][2] = 0.f; oc[j][3] = 0.f; }
    float m0 = 0.f, m1 = 0.f, l0 = 1.f, l1 = 1.f;   // ghost logit state

    for (int kt = 0; kt <= ktmax; kt++) {
        const int cur = kt & 1;
        if (kt < ktmax) {
            const int nxt = cur ^ 1;
            const float4* kp = kg + (size_t)(kt + 1) * 1024;
            const float4* vp = vg + (size_t)(kt + 1) * 2048;
            const uint32_t kdst = ksb + (uint32_t)nxt * 16384u;
            const uint32_t vdst = vsb + (uint32_t)nxt * 32768u;
#pragma unroll
            for (int i0 = 0; i0 < 4; i0++) {
                int i = i0 * 256 + tid;
                int row = i >> 4, c4 = i & 15;
                CP16(kdst + (((row << 4) + (c4 ^ (row & 7))) << 4), kp + i);
            }
#pragma unroll
            for (int i0 = 0; i0 < 8; i0++) {
                int i = i0 * 256 + tid;
                int row = i >> 5, c4 = i & 31;
                CP16(vdst + (((row << 5) + (c4 ^ ((row & 3) << 1))) << 4), vp + i);
            }
            CP_COMMIT();
            CP_WAIT1();
        } else {
            CP_WAIT0();
        }
        __syncthreads();

        float* Kc = Ks + cur * 4096;
        float* Vc = Vs + cur * 8192;

        // ---- in-place RNA tf32 rounding of K tile (bias-sensitive operand) ----
        {
            float4* Kc4 = reinterpret_cast<float4*>(Kc);
#pragma unroll
            for (int i0 = 0; i0 < 4; i0++) {
                int i = i0 * 256 + tid;
                float4 val = Kc4[i];
                val.x = __uint_as_float(f2tf(val.x));
                val.y = __uint_as_float(f2tf(val.y));
                val.z = __uint_as_float(f2tf(val.z));
                val.w = __uint_as_float(f2tf(val.w));
                Kc4[i] = val;
            }
        }
        __syncthreads();

        if (kt == 0) {
            // extract Q A-fragments (scale + RNA tf32)
            int row0 = (wm * 16 + r) << 6;
            int row1 = row0 + (8 << 6);
            int swz = r << 2;
#pragma unroll
            for (int kk = 0; kk < 8; kk++) {
                int d0 = kk * 8 + qd, d1 = d0 + 4;
                qa[kk][0] = f2tf(Qs[row0 + (d0 ^ swz)] * scale);
                qa[kk][1] = f2tf(Qs[row1 + (d0 ^ swz)] * scale);
                qa[kk][2] = f2tf(Qs[row0 + (d1 ^ swz)] * scale);
                qa[kk][3] = f2tf(Qs[row1 + (d1 ^ swz)] * scale);
            }
        }

        const bool active = (kt * 64 <= W0 + 15);
        if (active) {
            // ---- S = Q @ K^T ----
            float sc[8][4];
#pragma unroll
            for (int jn = 0; jn < 8; jn++) {
                float c0 = 0.f, c1 = 0.f, c2 = 0.f, c3 = 0.f;
                int keyr = (jn * 8 + r) << 6;
                int swz = r << 2;
#pragma unroll
                for (int kk = 0; kk < 8; kk++) {
                    uint32_t b0 = __float_as_uint(Kc[keyr + ((kk * 8 + qd) ^ swz)]);
                    uint32_t b1 = __float_as_uint(Kc[keyr + ((kk * 8 + qd + 4) ^ swz)]);
                    mma8(c0, c1, c2, c3, qa[kk][0], qa[kk][1], qa[kk][2], qa[kk][3], b0, b1);
                }
                sc[jn][0] = c0; sc[jn][1] = c1; sc[jn][2] = c2; sc[jn][3] = c3;
            }

            // ---- causal mask ----
            if (kt * 64 + 63 > W0) {
                int grow0 = W0 + r;
#pragma unroll
                for (int jn = 0; jn < 8; jn++) {
                    int gc = kt * 64 + jn * 8 + 2 * qd;
                    if (gc     > grow0)     sc[jn][0] = -1e30f;
                    if (gc + 1 > grow0)     sc[jn][1] = -1e30f;
                    if (gc     > grow0 + 8) sc[jn][2] = -1e30f;
                    if (gc + 1 > grow0 + 8) sc[jn][3] = -1e30f;
                }
            }

            // ---- online ghost-softmax ----
            float rm0 = -1e30f, rm1 = -1e30f;
#pragma unroll
            for (int jn = 0; jn < 8; jn++) {
                rm0 = fmaxf(rm0, fmaxf(sc[jn][0], sc[jn][1]));
                rm1 = fmaxf(rm1, fmaxf(sc[jn][2], sc[jn][3]));
            }
            rm0 = fmaxf(rm0, __shfl_xor_sync(F, rm0, 1));
            rm0 = fmaxf(rm0, __shfl_xor_sync(F, rm0, 2));
            rm1 = fmaxf(rm1, __shfl_xor_sync(F, rm1, 1));
            rm1 = fmaxf(rm1, __shfl_xor_sync(F, rm1, 2));
            float mn0 = fmaxf(m0, rm0), mn1 = fmaxf(m1, rm1);
            float al0 = __expf(m0 - mn0), al1 = __expf(m1 - mn1);
            m0 = mn0; m1 = mn1;

            float rs0 = 0.f, rs1 = 0.f;
#pragma unroll
            for (int jn = 0; jn < 8; jn++) {
                sc[jn][0] = __expf(sc[jn][0] - mn0); rs0 += sc[jn][0];
                sc[jn][1] = __expf(sc[jn][1] - mn0); rs0 += sc[jn][1];
                sc[jn][2] = __expf(sc[jn][2] - mn1); rs1 += sc[jn][2];
                sc[jn][3] = __expf(sc[jn][3] - mn1); rs1 += sc[jn][3];
            }
            rs0 += __shfl_xor_sync(F, rs0, 1);
            rs0 += __shfl_xor_sync(F, rs0, 2);
            rs1 += __shfl_xor_sync(F, rs1, 1);
            rs1 += __shfl_xor_sync(F, rs1, 2);
            l0 = l0 * al0 + rs0;
            l1 = l1 * al1 + rs1;

#pragma unroll
            for (int jo = 0; jo < 16; jo++) {
                oc[jo][0] *= al0; oc[jo][1] *= al0;
                oc[jo][2] *= al1; oc[jo][3] *= al1;
            }

            // ---- O += P @ V ----
            const int srcA = (lane & ~3) | (qd >> 1);
            const int srcB = srcA + 2;
            const bool odd = qd & 1;
#pragma unroll
            for (int kk2 = 0; kk2 < 8; kk2++) {
                float x00 = __shfl_sync(F, sc[kk2][0], srcA);
                float x01 = __shfl_sync(F, sc[kk2][1], srcA);
                float x20 = __shfl_sync(F, sc[kk2][2], srcA);
                float x21 = __shfl_sync(F, sc[kk2][3], srcA);
                float y00 = __shfl_sync(F, sc[kk2][0], srcB);
                float y01 = __shfl_sync(F, sc[kk2][1], srcB);
                float y20 = __shfl_sync(F, sc[kk2][2], srcB);
                float y21 = __shfl_sync(F, sc[kk2][3], srcB);
                uint32_t pa0 = f2tf(odd ? x01 : x00);
                uint32_t pa1 = f2tf(odd ? x21 : x20);
                uint32_t pa2 = f2tf(odd ? y01 : y00);
                uint32_t pa3 = f2tf(odd ? y21 : y20);
                int vr0 = (kk2 * 8 + qd) << 7;
                int vr1 = vr0 + (4 << 7);
                int swzv = qd << 3;
#pragma unroll
                for (int jo = 0; jo < 16; jo++) {
                    uint32_t b0 = __float_as_uint(Vc[vr0 + ((jo * 8 + r) ^ swzv)]);
                    uint32_t b1 = __float_as_uint(Vc[vr1 + ((jo * 8 + r) ^ swzv)]);
                    mma8(oc[jo][0], oc[jo][1], oc[jo][2], oc[jo][3], pa0, pa1, pa2, pa3, b0, b1);
                }
            }
        }
        __syncthreads();   // buffer reuse guard
    }

    // ---- epilogue: /l, stage to smem, coalesced store ----
    {
        float inv0 = 1.f / l0, inv1 = 1.f / l1;
        int row0 = wm * 16 + r, row1 = row0 + 8;
        int s0 = (r & 3) << 3;
#pragma unroll
        for (int jo = 0; jo < 16; jo++) {
            int c = jo * 8 + 2 * qd;
            int cs = c ^ s0;
            *reinterpret_cast<float2*>(&Ost[(row0 << 7) + cs]) =
                make_float2(oc[jo][0] * inv0, oc[jo][1] * inv0);
            *reinterpret_cast<float2*>(&Ost[(row1 << 7) + cs]) =
                make_float2(oc[jo][2] * inv1, oc[jo][3] * inv1);
        }
    }
    __syncthreads();
    {
        float4* op = reinterpret_cast<float4*>(
            g_o + (((size_t)b * HQ_ + h) * S_ + (size_t)qt * 128) * DV_);
        const float4* Os4 = reinterpret_cast<const float4*>(Ost);
#pragma unroll
        for (int i0 = 0; i0 < 16; i0++) {
            int i = i0 * 256 + tid;
            int row = i >> 5, c4 = i & 31;
            op[i] = Os4[(row << 5) + (c4 ^ ((row & 3) << 1))];
        }
    }
}

// ---------------------------------------------------------------------------
__global__ void lam_kernel(const float* __restrict__ lq1, const float* __restrict__ lk1,
                           const float* __restrict__ lq2, const float* __restrict__ lk2) {
    __shared__ float a[64], c[64];
    int t = threadIdx.x;
    a[t] = lq1[t] * lk1[t];
    c[t] = lq2[t] * lk2[t];
    __syncthreads();
    if (t == 0) {
        float s1 = 0.f, s2 = 0.f;
        for (int j = 0; j < 64; j++) { s1 += a[j]; s2 += c[j]; }
        g_lam = expf(s1) - expf(s2) + 0.8f;
    }
}

__global__ void stats_partial_kernel() {
    int g = blockIdx.x >> 3, p = blockIdx.x & 7;
    int b = g >> 4, gg = g & 15, hp = gg >> 1, half = gg & 1;
    const float* o0 = g_o + (((size_t)(b * 16 + 2 * hp)) * S_ + (size_t)half * 1024) * DV_;
    const float* o1 = o0 + (size_t)S_ * DV_;
    float lam = g_lam;
    double sum = 0.0, sq = 0.0;
    int base = p * (GROUP_ELEMS / PPG);
    for (int j = threadIdx.x; j < GROUP_ELEMS / PPG; j += 256) {
        float d = o0[base + j] - lam * o1[base + j];
        sum += (double)d;
        sq  += (double)d * (double)d;
    }
    __shared__ double ssum[256], ssq[256];
    ssum[threadIdx.x] = sum; ssq[threadIdx.x] = sq;
    __syncthreads();
    for (int st = 128; st > 0; st >>= 1) {
        if (threadIdx.x < st) {
            ssum[threadIdx.x] += ssum[threadIdx.x + st];
            ssq[threadIdx.x]  += ssq[threadIdx.x + st];
        }
        __syncthreads();
    }
    if (threadIdx.x == 0) {
        g_psum[blockIdx.x] = ssum[0];
        g_psq[blockIdx.x]  = ssq[0];
    }
}

__global__ void stats_final_kernel() {
    int g = threadIdx.x;
    double s = 0.0, sq = 0.0;
    for (int p = 0; p < PPG; p++) { s += g_psum[g * PPG + p]; sq += g_psq[g * PPG + p]; }
    double mean = s / (double)GROUP_ELEMS;
    double var  = sq / (double)GROUP_ELEMS - mean * mean;
    g_mean[g] = (float)mean;
    g_istd[g] = (float)(1.0 / sqrt(var + 1e-5));
}

__global__ void normalize_kernel(const float* __restrict__ gw, const float* __restrict__ gb,
                                 float* __restrict__ out) {
    int i = blockIdx.x * 256 + threadIdx.x;
    int dv = i & 127;
    int s  = (i >> 7) & 2047;
    int hp = (i >> 18) & 7;
    int b  = i >> 21;
    int g  = b * 16 + hp * 2 + (s >> 10);
    int c  = hp * 128 + (s >> 4);
    size_t i0 = (((size_t)(b * 16 + 2 * hp)) * S_ + s) * DV_ + dv;
    float lam = g_lam;
    float d = g_o[i0] - lam * g_o[i0 + (size_t)S_ * DV_];
    out[i] = ((d - g_mean[g]) * g_istd[g] * gw[c] + gb[c]) * 0.2f;
}

// ---------------------------------------------------------------------------
extern "C" void kernel_launch(void* const* d_in, const int* in_sizes, int n_in,
                              void* d_out, int out_size) {
    const float* q   = (const float*)d_in[0];
    const float* k   = (const float*)d_in[1];
    const float* v   = (const float*)d_in[2];
    const float* lq1 = (const float*)d_in[3];
    const float* lk1 = (const float*)d_in[4];
    const float* lq2 = (const float*)d_in[5];
    const float* lk2 = (const float*)d_in[6];
    const float* gw  = (const float*)d_in[7];
    const float* gb  = (const float*)d_in[8];
    float* out = (float*)d_out;

    cudaFuncSetAttribute(attn_kernel, cudaFuncAttributeMaxDynamicSharedMemorySize, 131072);
    attn_kernel<<<dim3(S_ / 128, HQ_, B_), 256, 131072>>>(q, k, v);
    lam_kernel<<<1, 64>>>(lq1, lk1, lq2, lk2);
    stats_partial_kernel<<<GROUPS * PPG, 256>>>();
    stats_final_kernel<<<1, 32>>>();
    normalize_kernel<<<(B_ * (HQ_ / 2) * S_ * DV_) / 256, 256>>>(gw, gb, out);
}